// round 16
// baseline (speedup 1.0000x reference)
#include <cuda_runtime.h>
#include <cuda_fp16.h>
#include <cstdint>
#include <cstddef>

// ---------------- problem constants ----------------
#define DD     1024
#define PCOLS  405       // 1 + 80 + 324
#define NTILE  4
#define BNL    104       // live cols per tile
#define BNP    112       // padded rows per tile
#define NF     300
#define NMAX   65536
#define BM     128
#define BK     64        // fp16: 64 halves = 128B rows -> SW128 swizzle
#define NCHUNK (DD / BK) // 16
#define NSTAGE 3
#define NSLICE 4

#define A_BYTES  (BM * 128)              // 16384
#define B_BYTES  (BNP * 128)             // 14336
#define STAGE_SZ (A_BYTES + B_BYTES)     // 30720
#define SMEM_DYN (1024 + NSTAGE * STAGE_SZ)  // 93184 -> 2 CTAs/SM
#define LDC      120

// ---------------- device scratch ----------------
__device__ __half g_xh[(size_t)NMAX * DD];        // 128 MB fp16 x
__device__ __half g_Wh[(size_t)NTILE * BNP * DD];
__device__ float  g_bias[NTILE * BNP];

// ---------------- helpers ----------------
__device__ __forceinline__ uint32_t smem_u32(const void* p) {
    uint32_t a;
    asm("{ .reg .u64 t; cvta.to.shared.u64 t, %1; cvt.u32.u64 %0, t; }" : "=r"(a) : "l"(p));
    return a;
}
__device__ __forceinline__ void cpa16(uint32_t dst, const void* src) {
    asm volatile("cp.async.cg.shared.global [%0], [%1], 16;" :: "r"(dst), "l"(src));
}
__device__ __forceinline__ void ldsm4(uint32_t r[4], uint32_t addr) {
    asm volatile("ldmatrix.sync.aligned.m8n8.x4.shared.b16 {%0,%1,%2,%3}, [%4];"
        : "=r"(r[0]), "=r"(r[1]), "=r"(r[2]), "=r"(r[3]) : "r"(addr));
}
__device__ __forceinline__ void mma16(float d[4], const uint32_t a[4], uint32_t b0, uint32_t b1) {
    asm volatile(
        "mma.sync.aligned.m16n8k16.row.col.f32.f16.f16.f32 "
        "{%0,%1,%2,%3}, {%4,%5,%6,%7}, {%8,%9}, {%0,%1,%2,%3};"
        : "+f"(d[0]), "+f"(d[1]), "+f"(d[2]), "+f"(d[3])
        : "r"(a[0]), "r"(a[1]), "r"(a[2]), "r"(a[3]), "r"(b0), "r"(b1));
}
__device__ __forceinline__ uint4 pack8(float4 a, float4 b) {
    __half2 h0 = __floats2half2_rn(a.x, a.y);
    __half2 h1 = __floats2half2_rn(a.z, a.w);
    __half2 h2 = __floats2half2_rn(b.x, b.y);
    __half2 h3 = __floats2half2_rn(b.z, b.w);
    uint4 u;
    u.x = *reinterpret_cast<uint32_t*>(&h0);
    u.y = *reinterpret_cast<uint32_t*>(&h1);
    u.z = *reinterpret_cast<uint32_t*>(&h2);
    u.w = *reinterpret_cast<uint32_t*>(&h3);
    return u;
}

// ---------------- k_cvt: x fp32 -> fp16, streaming, slice [i0, i0+cnt) ----------
__global__ void k_cvt(const float4* __restrict__ xi, int i0, int n8) {
    uint4* xo = reinterpret_cast<uint4*>(g_xh);
    int i = i0 + blockIdx.x * blockDim.x + threadIdx.x;
    if (i < n8) {
        float4 a = xi[2 * i], b = xi[2 * i + 1];
        xo[i] = pack8(a, b);
    }
}

// ---------------- k_fold: R12 exact — grid (8 cols x 20 rows), 128 thr ----------
__global__ void k_fold(const float* __restrict__ Wsem, const float* __restrict__ bsem,
                       const float* __restrict__ semm) {
    __shared__ float ssm[4 * NF];
    __shared__ float sscale[4];
    const int cg = blockIdx.x;        // 0..7 (128 cols)
    const int rg = blockIdx.y;        // 0..19 (4 rows)
    const int t = threadIdx.x, wid = t >> 5, lane = t & 31;
    const int r0 = rg * 4, c0 = cg * 128;

    {   // warp w -> norm of row w
        const float* src = semm + (size_t)(r0 + wid) * NF;
        float ss = 0.f;
        for (int f = lane; f < NF; f += 32) { float v = src[f]; ss += v * v; }
        for (int o = 16; o; o >>= 1) ss += __shfl_xor_sync(~0u, ss, o);
        if (lane == 0) sscale[wid] = 8.0f * rsqrtf(ss);
    }
    __syncthreads();
    for (int idx = t; idx < 4 * NF; idx += 128) {
        int ri = idx / NF, f = idx - ri * NF;
        ssm[ri * NF + f] = semm[(size_t)(r0 + ri) * NF + f] * sscale[ri];
    }
    __syncthreads();

    float acc[4] = {0.f, 0.f, 0.f, 0.f};
    const float* wp = Wsem + c0 + t;
#pragma unroll 10
    for (int f = 0; f < NF; f++) {
        float w = wp[(size_t)f * DD];
#pragma unroll
        for (int ri = 0; ri < 4; ri++) acc[ri] += ssm[ri * NF + f] * w;
    }
#pragma unroll
    for (int ri = 0; ri < 4; ri++)
        g_Wh[(size_t)(1 + r0 + ri) * DD + c0 + t] = __float2half_rn(acc[ri]);

    if (cg == 0) {   // warp w -> bias of row w
        float bb = 0.f;
        for (int f = lane; f < NF; f += 32) bb += ssm[wid * NF + f] * bsem[f];
        for (int o = 16; o; o >>= 1) bb += __shfl_xor_sync(~0u, bb, o);
        if (lane == 0) g_bias[1 + r0 + wid] = bb;
    }
}

// ---------------- k_copy: R12 exact ----------------
__global__ void k_copy(const float* __restrict__ Wcls, const float* __restrict__ bcls,
                       const float* __restrict__ Wbb,  const float* __restrict__ bbb) {
    const int p = blockIdx.x, t = threadIdx.x;
    const int tile = p / BNP, r = p - tile * BNP;
    const int j = tile * BNL + r;
    __half* wo = g_Wh + (size_t)p * DD;
    if (r >= BNL || j >= PCOLS) {
        for (int d = t; d < DD; d += 256) wo[d] = __float2half_rn(0.f);
        if (t == 0) g_bias[p] = 0.f;
    } else if (j == 0) {
        for (int d = t; d < DD; d += 256) wo[d] = __float2half_rn(Wcls[d]);
        if (t == 0) g_bias[p] = bcls[0];
    } else if (j <= 80) {
        // written by k_fold
    } else {
        const int i = j - 81;
        for (int d = t; d < DD; d += 256) wo[d] = __float2half_rn(Wbb[(size_t)i * DD + d]);
        if (t == 0) g_bias[p] = bbb[i];
    }
}

// ---------------- main GEMM: R13/R15 exact body (182.7us measured) --------------
__device__ __forceinline__ void issueA(uint32_t sbase, const __half* __restrict__ xs, int tid) {
#pragma unroll
    for (int i = 0; i < 4; i++) {
        int seg = tid + i * 256;
        int row = seg >> 3, q = seg & 7;
        cpa16(sbase + (uint32_t)(row * 128 + ((q ^ (row & 7)) << 4)),
              xs + (size_t)row * DD + q * 8);
    }
}
__device__ __forceinline__ void issueB(uint32_t sbase, const __half* __restrict__ ws, int tid) {
#pragma unroll
    for (int i = 0; i < 4; i++) {
        int seg = tid + i * 256;
        if (seg < BNP * 8) {
            int row = seg >> 3, q = seg & 7;
            cpa16(sbase + (uint32_t)(A_BYTES + row * 128 + ((q ^ (row & 7)) << 4)),
                  ws + (size_t)row * DD + q * 8);
        }
    }
    asm volatile("cp.async.commit_group;" ::: "memory");
}

template <int NJ0, int NJ1, int NB1, int LIVE>
__device__ __forceinline__ void gemm_body(char* sm, float* __restrict__ out, int N,
                                          int nt, int band0) {
    const int tid = threadIdx.x, wid = tid >> 5, lane = tid & 31;
    const int warp_m = wid & 3;
    const int warp_n = wid >> 2;
    const size_t row0 = (size_t)(band0 + blockIdx.y) * BM;
    const size_t NS = (size_t)N * 81;
    const int NJ = warp_n ? NJ1 : NJ0;
    const int colbase = warp_n ? NB1 : 0;

    float* sBias = (float*)sm;
    for (int i = tid; i < BNP; i += 256) sBias[i] = g_bias[nt * BNP + i];

    uint32_t st[NSTAGE];
#pragma unroll
    for (int s = 0; s < NSTAGE; s++) st[s] = smem_u32(sm + 1024 + s * STAGE_SZ);

    const __half* xrow0 = g_xh + row0 * DD;
    const __half* wrow0 = g_Wh + (size_t)nt * BNP * DD;

    const int rAr = warp_m * 32 + ((lane >> 3) & 1) * 8 + (lane & 7);
    const int qbA = lane >> 4;
    const uint32_t abase0 = (uint32_t)rAr * 128, abase1 = (uint32_t)(rAr + 16) * 128;
    const uint32_t axor = (uint32_t)(rAr & 7);
    const int rBr = colbase + (lane >> 4) * 8 + (lane & 7);
    const int qbB = (lane >> 3) & 1;
    uint32_t bbase[4];
#pragma unroll
    for (int g = 0; g < 4; g++) bbase[g] = (uint32_t)(rBr + g * 16) * 128;
    const uint32_t bxor = (uint32_t)(rBr & 7);

    float acc[2][NJ0][4];
#pragma unroll
    for (int mi = 0; mi < 2; mi++)
#pragma unroll
        for (int nj = 0; nj < NJ0; nj++)
#pragma unroll
            for (int e = 0; e < 4; e++) acc[mi][nj][e] = 0.f;

    issueA(st[0], xrow0, tid);           issueB(st[0], wrow0, tid);
    issueA(st[1], xrow0 + BK, tid);      issueB(st[1], wrow0 + BK, tid);

    for (int c = 0; c < NCHUNK; c++) {
        uint32_t Ab = st[c % NSTAGE], Bb = Ab + A_BYTES;
        if (c == NCHUNK - 1) asm volatile("cp.async.wait_group 0;" ::: "memory");
        else                 asm volatile("cp.async.wait_group 1;" ::: "memory");
        __syncthreads();
        const bool pre = (c + 2 < NCHUNK);
        const uint32_t stn = st[(c + 2) % NSTAGE];

#pragma unroll
        for (int kq = 0; kq < 4; kq++) {
            uint32_t a0[4], a1[4];
            uint32_t qsel = (uint32_t)((2 * kq + qbA) ^ axor) << 4;
            ldsm4(a0, Ab + abase0 + qsel);
            ldsm4(a1, Ab + abase1 + qsel);
            uint32_t qselB = (uint32_t)((2 * kq + qbB) ^ bxor) << 4;
            if (warp_n == 0) {
#pragma unroll
                for (int g = 0; g < 4; g++) {
                    if (g < (NJ0 + 1) / 2) {
                        uint32_t b[4];
                        ldsm4(b, Bb + bbase[g] + qselB);
                        if (2 * g < NJ0)     { mma16(acc[0][2 * g],     a0, b[0], b[1]);
                                               mma16(acc[1][2 * g],     a1, b[0], b[1]); }
                        if (2 * g + 1 < NJ0) { mma16(acc[0][2 * g + 1], a0, b[2], b[3]);
                                               mma16(acc[1][2 * g + 1], a1, b[2], b[3]); }
                    }
                }
            } else {
#pragma unroll
                for (int g = 0; g < 4; g++) {
                    if (g < (NJ1 + 1) / 2) {
                        uint32_t b[4];
                        ldsm4(b, Bb + bbase[g] + qselB);
                        if (2 * g < NJ1)     { mma16(acc[0][2 * g],     a0, b[0], b[1]);
                                               mma16(acc[1][2 * g],     a1, b[0], b[1]); }
                        if (2 * g + 1 < NJ1) { mma16(acc[0][2 * g + 1], a0, b[2], b[3]);
                                               mma16(acc[1][2 * g + 1], a1, b[2], b[3]); }
                    }
                }
            }
            if (kq == 0 && pre) issueA(stn, xrow0 + (size_t)(c + 2) * BK, tid);
            if (kq == 1 && pre) issueB(stn, wrow0 + (size_t)(c + 2) * BK, tid);
        }
    }
    __syncthreads();

    // ---- epilogue ----
    float* sC = (float*)(sm + 1024);
    const int tr = lane >> 2, tc2 = (lane & 3) * 2;
#pragma unroll
    for (int mi = 0; mi < 2; mi++)
#pragma unroll
        for (int nj = 0; nj < NJ0; nj++)
            if (nj < NJ) {
                int r = warp_m * 32 + mi * 16 + tr;
                int cc = colbase + nj * 8 + tc2;
                *(float2*)&sC[r * LDC + cc]       = make_float2(acc[mi][nj][0], acc[mi][nj][1]);
                *(float2*)&sC[(r + 8) * LDC + cc] = make_float2(acc[mi][nj][2], acc[mi][nj][3]);
            }
    __syncthreads();

    float* outb = out + NS;
    const int jbase = nt * BNL;
    for (int e = tid; e < BM * LIVE; e += 256) {
        int row = e / LIVE, n = e - row * LIVE;
        int j = jbase + n;
        float v = sC[row * LDC + n] + sBias[n];
        size_t gr = row0 + row;
        if (j < 81) __stcs(&out[gr * 81 + j], v);
        else        __stcs(&outb[gr * 324 + (j - 81)], v);
    }
}

__global__ __launch_bounds__(256, 2) void k_main(float* __restrict__ out, int N, int band0) {
    extern __shared__ char sm[];
    const int nt = blockIdx.x;
    if (nt < 3) gemm_body<7, 6, 56, 104>(sm, out, N, nt, band0);
    else        gemm_body<6, 6, 48, 93>(sm, out, N, nt, band0);
}

// ---------------- launch: multi-stream fork/join pipeline ----------------
extern "C" void kernel_launch(void* const* d_in, const int* in_sizes, int n_in,
                              void* d_out, int out_size) {
    const float* x    = (const float*)d_in[0];
    const float* Wcls = (const float*)d_in[1];
    const float* bcls = (const float*)d_in[2];
    const float* Wsem = (const float*)d_in[3];
    const float* bsem = (const float*)d_in[4];
    const float* Wbb  = (const float*)d_in[5];
    const float* bbb  = (const float*)d_in[6];
    const float* semm = (const float*)d_in[7];
    float* out = (float*)d_out;
    int N = in_sizes[0] / DD;

    static cudaStream_t s1 = nullptr;
    static cudaEvent_t evFork, evJoin, evC[NSLICE];
    static bool smset = false;
    if (!s1) {
        cudaStreamCreateWithFlags(&s1, cudaStreamNonBlocking);
        cudaEventCreateWithFlags(&evFork, cudaEventDisableTiming);
        cudaEventCreateWithFlags(&evJoin, cudaEventDisableTiming);
        for (int i = 0; i < NSLICE; i++)
            cudaEventCreateWithFlags(&evC[i], cudaEventDisableTiming);
    }
    if (!smset) {
        cudaFuncSetAttribute(k_main, cudaFuncAttributeMaxDynamicSharedMemorySize, SMEM_DYN);
        smset = true;
    }

    const int n8 = N * (DD / 8);
    const int nbands = N / BM;
    const int bands_sl = nbands / NSLICE;            // 128 for N=65536
    const int n8_sl = n8 / NSLICE;

    // fork: side stream gets fold + copy (independent of cvt)
    cudaEventRecord(evFork, 0);
    cudaStreamWaitEvent(s1, evFork, 0);
    k_fold<<<dim3(8, 20), 128, 0, s1>>>(Wsem, bsem, semm);
    k_copy<<<NTILE * BNP, 256, 0, s1>>>(Wcls, bcls, Wbb, bbb);

    // capture stream: cvt slices, each gated by an event
    for (int sl = 0; sl < NSLICE; sl++) {
        k_cvt<<<(n8_sl + 255) / 256, 256>>>((const float4*)x, sl * n8_sl, n8);
        cudaEventRecord(evC[sl], 0);
    }

    // side stream: main slices, each waits for its cvt slice (fold/copy ordered by stream)
    for (int sl = 0; sl < NSLICE; sl++) {
        cudaStreamWaitEvent(s1, evC[sl], 0);
        k_main<<<dim3(NTILE, bands_sl), 256, SMEM_DYN, s1>>>(out, N, sl * bands_sl);
    }

    // join
    cudaEventRecord(evJoin, s1);
    cudaStreamWaitEvent(0, evJoin, 0);
}

// round 17
// speedup vs baseline: 1.0281x; 1.0281x over previous
#include <cuda_runtime.h>
#include <cuda_fp16.h>
#include <cstdint>
#include <cstddef>

// ---------------- problem constants ----------------
#define DD     1024
#define PCOLS  405       // 1 + 80 + 324
#define NTILE  4
#define BNL    104       // live cols per tile
#define BNP    112       // padded rows per tile
#define NF     300
#define NMAX   65536
#define BM     128
#define BK     64        // fp16: 64 halves = 128B rows -> SW128 swizzle
#define NCHUNK (DD / BK) // 16
#define NSTAGE 3

#define A_BYTES  (BM * 128)              // 16384
#define B_BYTES  (BNP * 128)             // 14336
#define STAGE_SZ (A_BYTES + B_BYTES)     // 30720
#define SMEM_DYN (1024 + NSTAGE * STAGE_SZ)  // 93184 -> 2 CTAs/SM
#define LDC      120

// ---------------- device scratch ----------------
__device__ __half g_xh[(size_t)NMAX * DD];        // 128 MB fp16 x
__device__ __half g_Wh[(size_t)NTILE * BNP * DD];
__device__ float  g_bias[NTILE * BNP];

// ---------------- helpers ----------------
__device__ __forceinline__ uint32_t smem_u32(const void* p) {
    uint32_t a;
    asm("{ .reg .u64 t; cvta.to.shared.u64 t, %1; cvt.u32.u64 %0, t; }" : "=r"(a) : "l"(p));
    return a;
}
__device__ __forceinline__ void cpa16(uint32_t dst, const void* src) {
    asm volatile("cp.async.cg.shared.global [%0], [%1], 16;" :: "r"(dst), "l"(src));
}
__device__ __forceinline__ void ldsm4(uint32_t r[4], uint32_t addr) {
    asm volatile("ldmatrix.sync.aligned.m8n8.x4.shared.b16 {%0,%1,%2,%3}, [%4];"
        : "=r"(r[0]), "=r"(r[1]), "=r"(r[2]), "=r"(r[3]) : "r"(addr));
}
__device__ __forceinline__ void mma16(float d[4], const uint32_t a[4], uint32_t b0, uint32_t b1) {
    asm volatile(
        "mma.sync.aligned.m16n8k16.row.col.f32.f16.f16.f32 "
        "{%0,%1,%2,%3}, {%4,%5,%6,%7}, {%8,%9}, {%0,%1,%2,%3};"
        : "+f"(d[0]), "+f"(d[1]), "+f"(d[2]), "+f"(d[3])
        : "r"(a[0]), "r"(a[1]), "r"(a[2]), "r"(a[3]), "r"(b0), "r"(b1));
}
__device__ __forceinline__ void sts16(uint32_t addr, uint4 v) {
    asm volatile("st.shared.v4.b32 [%0], {%1,%2,%3,%4};"
        :: "r"(addr), "r"(v.x), "r"(v.y), "r"(v.z), "r"(v.w));
}
__device__ __forceinline__ uint4 pack8(float4 a, float4 b) {
    __half2 h0 = __floats2half2_rn(a.x, a.y);
    __half2 h1 = __floats2half2_rn(a.z, a.w);
    __half2 h2 = __floats2half2_rn(b.x, b.y);
    __half2 h3 = __floats2half2_rn(b.z, b.w);
    uint4 u;
    u.x = *reinterpret_cast<uint32_t*>(&h0);
    u.y = *reinterpret_cast<uint32_t*>(&h1);
    u.z = *reinterpret_cast<uint32_t*>(&h2);
    u.w = *reinterpret_cast<uint32_t*>(&h3);
    return u;
}

// ---------------- k_fold: R12 exact — grid (8 cols x 20 rows), 128 thr ----------
__global__ void k_fold(const float* __restrict__ Wsem, const float* __restrict__ bsem,
                       const float* __restrict__ semm) {
    __shared__ float ssm[4 * NF];
    __shared__ float sscale[4];
    const int cg = blockIdx.x;
    const int rg = blockIdx.y;
    const int t = threadIdx.x, wid = t >> 5, lane = t & 31;
    const int r0 = rg * 4, c0 = cg * 128;

    {
        const float* src = semm + (size_t)(r0 + wid) * NF;
        float ss = 0.f;
        for (int f = lane; f < NF; f += 32) { float v = src[f]; ss += v * v; }
        for (int o = 16; o; o >>= 1) ss += __shfl_xor_sync(~0u, ss, o);
        if (lane == 0) sscale[wid] = 8.0f * rsqrtf(ss);
    }
    __syncthreads();
    for (int idx = t; idx < 4 * NF; idx += 128) {
        int ri = idx / NF, f = idx - ri * NF;
        ssm[ri * NF + f] = semm[(size_t)(r0 + ri) * NF + f] * sscale[ri];
    }
    __syncthreads();

    float acc[4] = {0.f, 0.f, 0.f, 0.f};
    const float* wp = Wsem + c0 + t;
#pragma unroll 10
    for (int f = 0; f < NF; f++) {
        float w = wp[(size_t)f * DD];
#pragma unroll
        for (int ri = 0; ri < 4; ri++) acc[ri] += ssm[ri * NF + f] * w;
    }
#pragma unroll
    for (int ri = 0; ri < 4; ri++)
        g_Wh[(size_t)(1 + r0 + ri) * DD + c0 + t] = __float2half_rn(acc[ri]);

    if (cg == 0) {
        float bb = 0.f;
        for (int f = lane; f < NF; f += 32) bb += ssm[wid * NF + f] * bsem[f];
        for (int o = 16; o; o >>= 1) bb += __shfl_xor_sync(~0u, bb, o);
        if (lane == 0) g_bias[1 + r0 + wid] = bb;
    }
}

// ---------------- k_copy: R12 exact ----------------
__global__ void k_copy(const float* __restrict__ Wcls, const float* __restrict__ bcls,
                       const float* __restrict__ Wbb,  const float* __restrict__ bbb) {
    const int p = blockIdx.x, t = threadIdx.x;
    const int tile = p / BNP, r = p - tile * BNP;
    const int j = tile * BNL + r;
    __half* wo = g_Wh + (size_t)p * DD;
    if (r >= BNL || j >= PCOLS) {
        for (int d = t; d < DD; d += 256) wo[d] = __float2half_rn(0.f);
        if (t == 0) g_bias[p] = 0.f;
    } else if (j == 0) {
        for (int d = t; d < DD; d += 256) wo[d] = __float2half_rn(Wcls[d]);
        if (t == 0) g_bias[p] = bcls[0];
    } else if (j <= 80) {
        // written by k_fold
    } else {
        const int i = j - 81;
        for (int d = t; d < DD; d += 256) wo[d] = __float2half_rn(Wbb[(size_t)i * DD + d]);
        if (t == 0) g_bias[p] = bbb[i];
    }
}

// ---------------- shared B-issue ----------------
__device__ __forceinline__ void issueA(uint32_t sbase, const __half* __restrict__ xs, int tid) {
#pragma unroll
    for (int i = 0; i < 4; i++) {
        int seg = tid + i * 256;
        int row = seg >> 3, q = seg & 7;
        cpa16(sbase + (uint32_t)(row * 128 + ((q ^ (row & 7)) << 4)),
              xs + (size_t)row * DD + q * 8);
    }
}
__device__ __forceinline__ void issueB(uint32_t sbase, const __half* __restrict__ ws, int tid) {
#pragma unroll
    for (int i = 0; i < 4; i++) {
        int seg = tid + i * 256;
        if (seg < BNP * 8) {
            int row = seg >> 3, q = seg & 7;
            cpa16(sbase + (uint32_t)(A_BYTES + row * 128 + ((q ^ (row & 7)) << 4)),
                  ws + (size_t)row * DD + q * 8);
        }
    }
    asm volatile("cp.async.commit_group;" ::: "memory");
}

// ---------------- k_mainA: nt=0 GEMM with fused x conversion + g_xh writeout ----
__global__ __launch_bounds__(256, 2) void k_mainA(const float* __restrict__ x,
                                                  float* __restrict__ out, int N) {
    extern __shared__ char sm[];
    constexpr int NJ0 = 7, NJ1 = 6, NB1 = 56, LIVE = 104;
    const int tid = threadIdx.x, wid = tid >> 5, lane = tid & 31;
    const int warp_m = wid & 3;
    const int warp_n = wid >> 2;
    const size_t row0 = (size_t)blockIdx.y * BM;
    const size_t NS = (size_t)N * 81;
    const int NJ = warp_n ? NJ1 : NJ0;
    const int colbase = warp_n ? NB1 : 0;

    float* sBias = (float*)sm;
    for (int i = tid; i < BNP; i += 256) sBias[i] = g_bias[i];

    uint32_t st[NSTAGE];
#pragma unroll
    for (int s = 0; s < NSTAGE; s++) st[s] = smem_u32(sm + 1024 + s * STAGE_SZ);

    const float* xrow0 = x + row0 * DD;
    uint4* gx = reinterpret_cast<uint4*>(g_xh) + row0 * (DD / 8);
    const __half* wrow0 = g_Wh;      // tile 0

    uint32_t aoff[4]; uint32_t goff[4]; uint32_t gidx[4];
#pragma unroll
    for (int i = 0; i < 4; i++) {
        int seg = tid + i * 256;
        int row = seg >> 3, q = seg & 7;
        aoff[i] = (uint32_t)(row * 128 + ((q ^ (row & 7)) << 4));
        goff[i] = (uint32_t)(row * DD + q * 8);
        gidx[i] = (uint32_t)(row * 128 + q);
    }

    const int rAr = warp_m * 32 + ((lane >> 3) & 1) * 8 + (lane & 7);
    const int qbA = lane >> 4;
    const uint32_t abase0 = (uint32_t)rAr * 128, abase1 = (uint32_t)(rAr + 16) * 128;
    const uint32_t axor = (uint32_t)(rAr & 7);
    const int rBr = colbase + (lane >> 4) * 8 + (lane & 7);
    const int qbB = (lane >> 3) & 1;
    uint32_t bbase[4];
#pragma unroll
    for (int g = 0; g < 4; g++) bbase[g] = (uint32_t)(rBr + g * 16) * 128;
    const uint32_t bxor = (uint32_t)(rBr & 7);

    float acc[2][NJ0][4];
#pragma unroll
    for (int mi = 0; mi < 2; mi++)
#pragma unroll
        for (int nj = 0; nj < NJ0; nj++)
#pragma unroll
            for (int e = 0; e < 4; e++) acc[mi][nj][e] = 0.f;

    uint4 buf[4];
    // ---- prologue: chunk0 direct (+STG), chunk1 into buf (+STG) ----
    {
#pragma unroll
        for (int i = 0; i < 4; i++) {
            float4 ra = *(const float4*)(xrow0 + goff[i]);
            float4 rb = *(const float4*)(xrow0 + goff[i] + 4);
            uint4 u = pack8(ra, rb);
            sts16(st[0] + aoff[i], u);
            gx[gidx[i]] = u;
        }
        issueB(st[0], wrow0, tid);
#pragma unroll
        for (int i = 0; i < 4; i++) {
            float4 ra = *(const float4*)(xrow0 + BK + goff[i]);
            float4 rb = *(const float4*)(xrow0 + BK + goff[i] + 4);
            buf[i] = pack8(ra, rb);
            gx[8 + gidx[i]] = buf[i];
        }
        issueB(st[1], wrow0 + BK, tid);
    }

    for (int c = 0; c < NCHUNK; c++) {
        if (c == NCHUNK - 1) asm volatile("cp.async.wait_group 0;" ::: "memory");
        else                 asm volatile("cp.async.wait_group 1;" ::: "memory");
        __syncthreads();
        const uint32_t Ab = st[c % NSTAGE], Bb = Ab + A_BYTES;

        if (c + 1 < NCHUNK) {
            uint32_t dstA = st[(c + 1) % NSTAGE];
#pragma unroll
            for (int i = 0; i < 4; i++) sts16(dstA + aoff[i], buf[i]);
        }
        const bool pre = (c + 2 < NCHUNK);
        const float* xs = xrow0 + (c + 2) * BK;
        float4 r0a, r0b, r1a, r1b;
        if (pre) {
            r0a = *(const float4*)(xs + goff[0]);
            r0b = *(const float4*)(xs + goff[0] + 4);
            r1a = *(const float4*)(xs + goff[1]);
            r1b = *(const float4*)(xs + goff[1] + 4);
            issueB(st[(c + 2) % NSTAGE], wrow0 + (size_t)(c + 2) * BK, tid);
        }

#pragma unroll
        for (int kq = 0; kq < 4; kq++) {
            uint32_t a0[4], a1[4];
            uint32_t qsel = (uint32_t)((2 * kq + qbA) ^ axor) << 4;
            ldsm4(a0, Ab + abase0 + qsel);
            ldsm4(a1, Ab + abase1 + qsel);
            uint32_t qselB = (uint32_t)((2 * kq + qbB) ^ bxor) << 4;
            if (warp_n == 0) {
#pragma unroll
                for (int g = 0; g < 4; g++) {
                    uint32_t b[4];
                    ldsm4(b, Bb + bbase[g] + qselB);
                    mma16(acc[0][2 * g], a0, b[0], b[1]);
                    mma16(acc[1][2 * g], a1, b[0], b[1]);
                    if (2 * g + 1 < NJ0) {
                        mma16(acc[0][2 * g + 1], a0, b[2], b[3]);
                        mma16(acc[1][2 * g + 1], a1, b[2], b[3]);
                    }
                }
            } else {
#pragma unroll
                for (int g = 0; g < 3; g++) {
                    uint32_t b[4];
                    ldsm4(b, Bb + bbase[g] + qselB);
                    mma16(acc[0][2 * g], a0, b[0], b[1]);
                    mma16(acc[1][2 * g], a1, b[0], b[1]);
                    mma16(acc[0][2 * g + 1], a0, b[2], b[3]);
                    mma16(acc[1][2 * g + 1], a1, b[2], b[3]);
                }
            }
            if (kq == 0 && pre) {
                buf[0] = pack8(r0a, r0b);
                buf[1] = pack8(r1a, r1b);
                gx[(size_t)(c + 2) * 8 + gidx[0]] = buf[0];
                gx[(size_t)(c + 2) * 8 + gidx[1]] = buf[1];
                r0a = *(const float4*)(xs + goff[2]);
                r0b = *(const float4*)(xs + goff[2] + 4);
                r1a = *(const float4*)(xs + goff[3]);
                r1b = *(const float4*)(xs + goff[3] + 4);
            }
            if (kq == 2 && pre) {
                buf[2] = pack8(r0a, r0b);
                buf[3] = pack8(r1a, r1b);
                gx[(size_t)(c + 2) * 8 + gidx[2]] = buf[2];
                gx[(size_t)(c + 2) * 8 + gidx[3]] = buf[3];
            }
        }
    }
    __syncthreads();

    // ---- epilogue ----
    float* sC = (float*)(sm + 1024);
    const int tr = lane >> 2, tc2 = (lane & 3) * 2;
#pragma unroll
    for (int mi = 0; mi < 2; mi++)
#pragma unroll
        for (int nj = 0; nj < NJ0; nj++)
            if (nj < NJ) {
                int r = warp_m * 32 + mi * 16 + tr;
                int cc = colbase + nj * 8 + tc2;
                *(float2*)&sC[r * LDC + cc]       = make_float2(acc[mi][nj][0], acc[mi][nj][1]);
                *(float2*)&sC[(r + 8) * LDC + cc] = make_float2(acc[mi][nj][2], acc[mi][nj][3]);
            }
    __syncthreads();

    float* outb = out + NS;
    for (int e = tid; e < BM * LIVE; e += 256) {
        int row = e / LIVE, n = e - row * LIVE;
        float v = sC[row * LDC + n] + sBias[n];
        size_t gr = row0 + row;
        if (n < 81) __stcs(&out[gr * 81 + n], v);
        else        __stcs(&outb[gr * 324 + (n - 81)], v);
    }
}

// ---------------- k_mainB: tiles 1-3, R15 exact body ----------------
template <int NJ0, int NJ1, int NB1, int LIVE>
__device__ __forceinline__ void gemm_body(char* sm, float* __restrict__ out, int N, int nt) {
    const int tid = threadIdx.x, wid = tid >> 5, lane = tid & 31;
    const int warp_m = wid & 3;
    const int warp_n = wid >> 2;
    const size_t row0 = (size_t)blockIdx.y * BM;
    const size_t NS = (size_t)N * 81;
    const int NJ = warp_n ? NJ1 : NJ0;
    const int colbase = warp_n ? NB1 : 0;

    float* sBias = (float*)sm;
    for (int i = tid; i < BNP; i += 256) sBias[i] = g_bias[nt * BNP + i];

    uint32_t st[NSTAGE];
#pragma unroll
    for (int s = 0; s < NSTAGE; s++) st[s] = smem_u32(sm + 1024 + s * STAGE_SZ);

    const __half* xrow0 = g_xh + row0 * DD;
    const __half* wrow0 = g_Wh + (size_t)nt * BNP * DD;

    const int rAr = warp_m * 32 + ((lane >> 3) & 1) * 8 + (lane & 7);
    const int qbA = lane >> 4;
    const uint32_t abase0 = (uint32_t)rAr * 128, abase1 = (uint32_t)(rAr + 16) * 128;
    const uint32_t axor = (uint32_t)(rAr & 7);
    const int rBr = colbase + (lane >> 4) * 8 + (lane & 7);
    const int qbB = (lane >> 3) & 1;
    uint32_t bbase[4];
#pragma unroll
    for (int g = 0; g < 4; g++) bbase[g] = (uint32_t)(rBr + g * 16) * 128;
    const uint32_t bxor = (uint32_t)(rBr & 7);

    float acc[2][NJ0][4];
#pragma unroll
    for (int mi = 0; mi < 2; mi++)
#pragma unroll
        for (int nj = 0; nj < NJ0; nj++)
#pragma unroll
            for (int e = 0; e < 4; e++) acc[mi][nj][e] = 0.f;

    issueA(st[0], xrow0, tid);           issueB(st[0], wrow0, tid);
    issueA(st[1], xrow0 + BK, tid);      issueB(st[1], wrow0 + BK, tid);

    for (int c = 0; c < NCHUNK; c++) {
        uint32_t Ab = st[c % NSTAGE], Bb = Ab + A_BYTES;
        if (c == NCHUNK - 1) asm volatile("cp.async.wait_group 0;" ::: "memory");
        else                 asm volatile("cp.async.wait_group 1;" ::: "memory");
        __syncthreads();
        const bool pre = (c + 2 < NCHUNK);
        const uint32_t stn = st[(c + 2) % NSTAGE];

#pragma unroll
        for (int kq = 0; kq < 4; kq++) {
            uint32_t a0[4], a1[4];
            uint32_t qsel = (uint32_t)((2 * kq + qbA) ^ axor) << 4;
            ldsm4(a0, Ab + abase0 + qsel);
            ldsm4(a1, Ab + abase1 + qsel);
            uint32_t qselB = (uint32_t)((2 * kq + qbB) ^ bxor) << 4;
            if (warp_n == 0) {
#pragma unroll
                for (int g = 0; g < 4; g++) {
                    if (g < (NJ0 + 1) / 2) {
                        uint32_t b[4];
                        ldsm4(b, Bb + bbase[g] + qselB);
                        if (2 * g < NJ0)     { mma16(acc[0][2 * g],     a0, b[0], b[1]);
                                               mma16(acc[1][2 * g],     a1, b[0], b[1]); }
                        if (2 * g + 1 < NJ0) { mma16(acc[0][2 * g + 1], a0, b[2], b[3]);
                                               mma16(acc[1][2 * g + 1], a1, b[2], b[3]); }
                    }
                }
            } else {
#pragma unroll
                for (int g = 0; g < 4; g++) {
                    if (g < (NJ1 + 1) / 2) {
                        uint32_t b[4];
                        ldsm4(b, Bb + bbase[g] + qselB);
                        if (2 * g < NJ1)     { mma16(acc[0][2 * g],     a0, b[0], b[1]);
                                               mma16(acc[1][2 * g],     a1, b[0], b[1]); }
                        if (2 * g + 1 < NJ1) { mma16(acc[0][2 * g + 1], a0, b[2], b[3]);
                                               mma16(acc[1][2 * g + 1], a1, b[2], b[3]); }
                    }
                }
            }
            if (kq == 0 && pre) issueA(stn, xrow0 + (size_t)(c + 2) * BK, tid);
            if (kq == 1 && pre) issueB(stn, wrow0 + (size_t)(c + 2) * BK, tid);
        }
    }
    __syncthreads();

    float* sC = (float*)(sm + 1024);
    const int tr = lane >> 2, tc2 = (lane & 3) * 2;
#pragma unroll
    for (int mi = 0; mi < 2; mi++)
#pragma unroll
        for (int nj = 0; nj < NJ0; nj++)
            if (nj < NJ) {
                int r = warp_m * 32 + mi * 16 + tr;
                int cc = colbase + nj * 8 + tc2;
                *(float2*)&sC[r * LDC + cc]       = make_float2(acc[mi][nj][0], acc[mi][nj][1]);
                *(float2*)&sC[(r + 8) * LDC + cc] = make_float2(acc[mi][nj][2], acc[mi][nj][3]);
            }
    __syncthreads();

    float* outb = out + NS;
    const int jbase = nt * BNL;
    for (int e = tid; e < BM * LIVE; e += 256) {
        int row = e / LIVE, n = e - row * LIVE;
        int j = jbase + n;
        float v = sC[row * LDC + n] + sBias[n];
        size_t gr = row0 + row;
        if (j < 81) __stcs(&out[gr * 81 + j], v);
        else        __stcs(&outb[gr * 324 + (j - 81)], v);
    }
}

__global__ __launch_bounds__(256, 2) void k_mainB(float* __restrict__ out, int N) {
    extern __shared__ char sm[];
    const int nt = blockIdx.x + 1;       // tiles 1..3
    if (nt < 3) gemm_body<7, 6, 56, 104>(sm, out, N, nt);
    else        gemm_body<6, 6, 48, 93>(sm, out, N, nt);
}

// ---------------- launch ----------------
extern "C" void kernel_launch(void* const* d_in, const int* in_sizes, int n_in,
                              void* d_out, int out_size) {
    const float* x    = (const float*)d_in[0];
    const float* Wcls = (const float*)d_in[1];
    const float* bcls = (const float*)d_in[2];
    const float* Wsem = (const float*)d_in[3];
    const float* bsem = (const float*)d_in[4];
    const float* Wbb  = (const float*)d_in[5];
    const float* bbb  = (const float*)d_in[6];
    const float* semm = (const float*)d_in[7];
    float* out = (float*)d_out;
    int N = in_sizes[0] / DD;

    cudaFuncSetAttribute(k_mainA, cudaFuncAttributeMaxDynamicSharedMemorySize, SMEM_DYN);
    cudaFuncSetAttribute(k_mainB, cudaFuncAttributeMaxDynamicSharedMemorySize, SMEM_DYN);

    k_fold<<<dim3(8, 20), 128>>>(Wsem, bsem, semm);
    k_copy<<<NTILE * BNP, 256>>>(Wcls, bcls, Wbb, bbb);
    k_mainA<<<dim3(1, N / BM), 256, SMEM_DYN>>>(x, out, N);
    k_mainB<<<dim3(3, N / BM), 256, SMEM_DYN>>>(out, N);
}